// round 1
// baseline (speedup 1.0000x reference)
#include <cuda_runtime.h>
#include <math.h>

#define N_NODES 40962
#define DIM 512
#define N_EDGES 655392
#define NB 4
#define NHEADS 4
#define DH 128
#define CDIM 16
#define NFREQ 32

// ---------------- scratch (device globals; no allocation allowed) ----------------
__device__ float g_y[(size_t)N_NODES * DIM];
__device__ float g_q[(size_t)N_NODES * DIM];
__device__ float g_k[(size_t)N_NODES * DIM];
__device__ float g_v[(size_t)N_NODES * DIM];
__device__ float g_attn[(size_t)N_NODES * DIM];
__device__ float g_h[(size_t)N_NODES * DIM];
__device__ float g_cond[(size_t)N_NODES * CDIM];
__device__ int g_deg[N_NODES];
__device__ int g_rowptr[N_NODES + 1];
__device__ int g_cursor[N_NODES];
__device__ int g_csrdst[N_EDGES];

// ---------------- CSR build ----------------
__global__ void k_zero_deg() {
    int i = blockIdx.x * blockDim.x + threadIdx.x;
    if (i < N_NODES) g_deg[i] = 0;
}

__global__ void k_count_deg(const int* __restrict__ edge) {
    int e = blockIdx.x * blockDim.x + threadIdx.x;
    if (e < N_EDGES) atomicAdd(&g_deg[edge[e]], 1);
}

__global__ void k_scan_deg() {
    __shared__ int partial[1024];
    const int tid = threadIdx.x;
    const int CH = (N_NODES + 1023) / 1024;   // 41
    const int base = tid * CH;
    int sum = 0;
    for (int i = 0; i < CH; i++) {
        int idx = base + i;
        if (idx < N_NODES) sum += g_deg[idx];
    }
    partial[tid] = sum;
    __syncthreads();
    // Hillis-Steele inclusive scan
    for (int off = 1; off < 1024; off <<= 1) {
        int t = (tid >= off) ? partial[tid - off] : 0;
        __syncthreads();
        partial[tid] += t;
        __syncthreads();
    }
    int offset = (tid > 0) ? partial[tid - 1] : 0;
    for (int i = 0; i < CH; i++) {
        int idx = base + i;
        if (idx < N_NODES) {
            g_rowptr[idx] = offset;
            g_cursor[idx] = offset;
            offset += g_deg[idx];
        }
    }
    if (tid == 1023) g_rowptr[N_NODES] = partial[1023];
}

__global__ void k_scatter_edges(const int* __restrict__ edge) {
    int e = blockIdx.x * blockDim.x + threadIdx.x;
    if (e < N_EDGES) {
        int s = edge[e];
        int d = edge[N_EDGES + e];
        int p = atomicAdd(&g_cursor[s], 1);
        g_csrdst[p] = d;
    }
}

// ---------------- Fourier noise embedding + cond MLP ----------------
__global__ void k_cond(const float* __restrict__ noise,
                       const float* __restrict__ fw1, const float* __restrict__ fb1,
                       const float* __restrict__ fw2, const float* __restrict__ fb2) {
    __shared__ float s_w1[2 * NFREQ * CDIM];   // 64x16
    __shared__ float s_w2[CDIM * CDIM];
    __shared__ float s_b1[CDIM];
    __shared__ float s_b2[CDIM];
    for (int i = threadIdx.x; i < 2 * NFREQ * CDIM; i += blockDim.x) s_w1[i] = fw1[i];
    for (int i = threadIdx.x; i < CDIM * CDIM; i += blockDim.x) s_w2[i] = fw2[i];
    if (threadIdx.x < CDIM) {
        s_b1[threadIdx.x] = fb1[threadIdx.x];
        s_b2[threadIdx.x] = fb2[threadIdx.x];
    }
    __syncthreads();
    int n = blockIdx.x * blockDim.x + threadIdx.x;
    if (n >= N_NODES) return;
    float t = noise[n];
    const float w0 = 2.0f * 3.14159265358979323846f / 16.0f;
    float emb[2 * NFREQ];
    #pragma unroll
    for (int f = 0; f < NFREQ; f++) {
        float ph = t * (w0 * (float)(f + 1));
        emb[f] = sinf(ph);
        emb[NFREQ + f] = cosf(ph);
    }
    float h[CDIM];
    #pragma unroll
    for (int c = 0; c < CDIM; c++) {
        float acc = s_b1[c];
        #pragma unroll
        for (int f = 0; f < 2 * NFREQ; f++) acc = fmaf(emb[f], s_w1[f * CDIM + c], acc);
        h[c] = acc / (1.0f + expf(-acc));   // silu
    }
    #pragma unroll
    for (int c2 = 0; c2 < CDIM; c2++) {
        float acc = s_b2[c2];
        #pragma unroll
        for (int c = 0; c < CDIM; c++) acc = fmaf(h[c], s_w2[c * CDIM + c2], acc);
        g_cond[n * CDIM + c2] = acc;
    }
}

// ---------------- conditional LayerNorm (FiLM), one block per node ----------------
__global__ void k_cln(const float* __restrict__ x,
                      const float* __restrict__ sw, const float* __restrict__ sb,
                      const float* __restrict__ bw, const float* __restrict__ bb) {
    int n = blockIdx.x;
    int tid = threadIdx.x;
    __shared__ float s_cond[CDIM];
    __shared__ float s_red[8];
    if (tid < CDIM) s_cond[tid] = g_cond[n * CDIM + tid];
    float4 xv = *(const float4*)(x + (size_t)n * DIM + tid * 4);
    float s = xv.x + xv.y + xv.z + xv.w;
    float s2 = fmaf(xv.x, xv.x, fmaf(xv.y, xv.y, fmaf(xv.z, xv.z, xv.w * xv.w)));
    #pragma unroll
    for (int o = 16; o; o >>= 1) {
        s += __shfl_xor_sync(0xffffffffu, s, o);
        s2 += __shfl_xor_sync(0xffffffffu, s2, o);
    }
    int w = tid >> 5, l = tid & 31;
    if (l == 0) { s_red[w] = s; s_red[4 + w] = s2; }
    __syncthreads();
    s = s_red[0] + s_red[1] + s_red[2] + s_red[3];
    s2 = s_red[4] + s_red[5] + s_red[6] + s_red[7];
    float mu = s * (1.0f / DIM);
    float var = s2 * (1.0f / DIM) - mu * mu;
    float inv = rsqrtf(var + 1e-5f);
    int d0 = tid * 4;
    float sc[4], bi[4];
    #pragma unroll
    for (int j = 0; j < 4; j++) { sc[j] = sb[d0 + j]; bi[j] = bb[d0 + j]; }
    #pragma unroll
    for (int c = 0; c < CDIM; c++) {
        float cv = s_cond[c];
        const float* swr = sw + c * DIM + d0;
        const float* bwr = bw + c * DIM + d0;
        #pragma unroll
        for (int j = 0; j < 4; j++) {
            sc[j] = fmaf(cv, swr[j], sc[j]);
            bi[j] = fmaf(cv, bwr[j], bi[j]);
        }
    }
    float4 out;
    out.x = (xv.x - mu) * inv * (1.0f + sc[0]) + bi[0];
    out.y = (xv.y - mu) * inv * (1.0f + sc[1]) + bi[1];
    out.z = (xv.z - mu) * inv * (1.0f + sc[2]) + bi[2];
    out.w = (xv.w - mu) * inv * (1.0f + sc[3]) + bi[3];
    *(float4*)(g_y + (size_t)n * DIM + d0) = out;
}

// ---------------- fp32 SGEMM: C[M,512] = A[M,512] @ W[512,512] + bias (+relu)(+res) ----
// flags: bit0 = relu, bit1 = residual add
__global__ __launch_bounds__(256) void k_gemm512(
    const float* __restrict__ A, const float* __restrict__ W,
    const float* __restrict__ Bias, const float* __restrict__ Res,
    float* __restrict__ C, int M, int flags) {
    __shared__ float As[16][132];
    __shared__ float Bs[16][128];
    const int tid = threadIdx.x;
    const int col0 = blockIdx.x * 128;
    const int row0 = blockIdx.y * 128;
    const int ty = tid >> 4, tx = tid & 15;
    const int crow = ty * 8, ccol = tx * 8;

    float acc[8][8];
    #pragma unroll
    for (int i = 0; i < 8; i++)
        #pragma unroll
        for (int j = 0; j < 8; j++) acc[i][j] = 0.0f;

    const int aRow = tid >> 2;        // 0..63
    const int aCol = (tid & 3) * 4;   // 0,4,8,12
    const int bRow = tid >> 5;        // 0..7
    const int bCol = (tid & 31) * 4;

    for (int k0 = 0; k0 < 512; k0 += 16) {
        #pragma unroll
        for (int r = 0; r < 2; r++) {
            int row = row0 + aRow + r * 64;
            float4 av = make_float4(0.f, 0.f, 0.f, 0.f);
            if (row < M) av = *(const float4*)(A + (size_t)row * 512 + k0 + aCol);
            As[aCol + 0][aRow + r * 64] = av.x;
            As[aCol + 1][aRow + r * 64] = av.y;
            As[aCol + 2][aRow + r * 64] = av.z;
            As[aCol + 3][aRow + r * 64] = av.w;
        }
        #pragma unroll
        for (int r = 0; r < 2; r++) {
            int kk = bRow + r * 8;
            float4 bv = *(const float4*)(W + (size_t)(k0 + kk) * 512 + col0 + bCol);
            *(float4*)(&Bs[kk][bCol]) = bv;
        }
        __syncthreads();
        #pragma unroll
        for (int k = 0; k < 16; k++) {
            float ar[8], br[8];
            float4 t0 = *(const float4*)(&As[k][crow]);
            float4 t1 = *(const float4*)(&As[k][crow + 4]);
            float4 u0 = *(const float4*)(&Bs[k][ccol]);
            float4 u1 = *(const float4*)(&Bs[k][ccol + 4]);
            ar[0] = t0.x; ar[1] = t0.y; ar[2] = t0.z; ar[3] = t0.w;
            ar[4] = t1.x; ar[5] = t1.y; ar[6] = t1.z; ar[7] = t1.w;
            br[0] = u0.x; br[1] = u0.y; br[2] = u0.z; br[3] = u0.w;
            br[4] = u1.x; br[5] = u1.y; br[6] = u1.z; br[7] = u1.w;
            #pragma unroll
            for (int i = 0; i < 8; i++)
                #pragma unroll
                for (int j = 0; j < 8; j++)
                    acc[i][j] = fmaf(ar[i], br[j], acc[i][j]);
        }
        __syncthreads();
    }

    const bool relu = (flags & 1) != 0;
    const bool resid = (flags & 2) != 0;
    #pragma unroll
    for (int i = 0; i < 8; i++) {
        int row = row0 + crow + i;
        if (row >= M) break;
        #pragma unroll
        for (int j = 0; j < 8; j += 4) {
            int col = col0 + ccol + j;
            float4 r;
            r.x = acc[i][j + 0] + Bias[col + 0];
            r.y = acc[i][j + 1] + Bias[col + 1];
            r.z = acc[i][j + 2] + Bias[col + 2];
            r.w = acc[i][j + 3] + Bias[col + 3];
            if (relu) {
                r.x = fmaxf(r.x, 0.f); r.y = fmaxf(r.y, 0.f);
                r.z = fmaxf(r.z, 0.f); r.w = fmaxf(r.w, 0.f);
            }
            if (resid) {
                float4 rv = *(const float4*)(Res + (size_t)row * 512 + col);
                r.x += rv.x; r.y += rv.y; r.z += rv.z; r.w += rv.w;
            }
            *(float4*)(C + (size_t)row * 512 + col) = r;
        }
    }
}

// ---------------- sparse attention: one block per node, one warp per head ----------
__global__ void k_attn() {
    int n = blockIdx.x;
    int warp = threadIdx.x >> 5;
    int lane = threadIdx.x & 31;
    int beg = g_rowptr[n], end = g_rowptr[n + 1];
    const float scale = 0.08838834764831845f;   // 1/sqrt(128)
    size_t base = (size_t)n * DIM + warp * DH + lane * 4;
    float4 qv = *(const float4*)&g_q[base];
    float m = -INFINITY, s = 0.0f;
    float a0 = 0.f, a1 = 0.f, a2 = 0.f, a3 = 0.f;
    for (int e = beg; e < end; e++) {
        int d = g_csrdst[e];
        size_t kb = (size_t)d * DIM + warp * DH + lane * 4;
        float4 kv = *(const float4*)&g_k[kb];
        float p = qv.x * kv.x + qv.y * kv.y + qv.z * kv.z + qv.w * kv.w;
        p += __shfl_xor_sync(0xffffffffu, p, 16);
        p += __shfl_xor_sync(0xffffffffu, p, 8);
        p += __shfl_xor_sync(0xffffffffu, p, 4);
        p += __shfl_xor_sync(0xffffffffu, p, 2);
        p += __shfl_xor_sync(0xffffffffu, p, 1);
        float score = p * scale;
        float4 vv = *(const float4*)&g_v[kb];
        float mn = fmaxf(m, score);
        float corr = expf(m - mn);    // exp(-inf)=0 handles first iter
        float w = expf(score - mn);
        s = s * corr + w;
        a0 = fmaf(w, vv.x, a0 * corr);
        a1 = fmaf(w, vv.y, a1 * corr);
        a2 = fmaf(w, vv.z, a2 * corr);
        a3 = fmaf(w, vv.w, a3 * corr);
        m = mn;
    }
    float inv = (end > beg) ? (1.0f / s) : 0.0f;
    float4 o = make_float4(a0 * inv, a1 * inv, a2 * inv, a3 * inv);
    *(float4*)&g_attn[base] = o;
}

// ---------------- host ----------------
extern "C" void kernel_launch(void* const* d_in, const int* in_sizes, int n_in,
                              void* d_out, int out_size) {
    const float* x_in  = (const float*)d_in[0];
    const int*   edge  = (const int*)d_in[1];
    const float* noise = (const float*)d_in[2];
    const float* f_w1 = (const float*)d_in[3];
    const float* f_b1 = (const float*)d_in[4];
    const float* f_w2 = (const float*)d_in[5];
    const float* f_b2 = (const float*)d_in[6];
    const float* s1_w = (const float*)d_in[7];
    const float* s1_b = (const float*)d_in[8];
    const float* b1_w = (const float*)d_in[9];
    const float* b1_b = (const float*)d_in[10];
    const float* wq = (const float*)d_in[11];
    const float* bq = (const float*)d_in[12];
    const float* wk = (const float*)d_in[13];
    const float* bk = (const float*)d_in[14];
    const float* wv = (const float*)d_in[15];
    const float* bv = (const float*)d_in[16];
    const float* wo = (const float*)d_in[17];
    const float* bo = (const float*)d_in[18];
    const float* s2_w = (const float*)d_in[19];
    const float* s2_b = (const float*)d_in[20];
    const float* b2_w = (const float*)d_in[21];
    const float* b2_b = (const float*)d_in[22];
    const float* m_w1 = (const float*)d_in[23];
    const float* m_b1 = (const float*)d_in[24];
    const float* m_w2 = (const float*)d_in[25];
    const float* m_b2 = (const float*)d_in[26];

    float* x = (float*)d_out;

    float *yp, *qp, *kp, *vp, *ap, *hp;
    cudaGetSymbolAddress((void**)&yp, g_y);
    cudaGetSymbolAddress((void**)&qp, g_q);
    cudaGetSymbolAddress((void**)&kp, g_k);
    cudaGetSymbolAddress((void**)&vp, g_v);
    cudaGetSymbolAddress((void**)&ap, g_attn);
    cudaGetSymbolAddress((void**)&hp, g_h);

    cudaMemcpyAsync(x, x_in, (size_t)N_NODES * DIM * sizeof(float),
                    cudaMemcpyDeviceToDevice);

    // CSR build (edge_index is an input; rebuild every call)
    k_zero_deg<<<(N_NODES + 255) / 256, 256>>>();
    k_count_deg<<<(N_EDGES + 255) / 256, 256>>>(edge);
    k_scan_deg<<<1, 1024>>>();
    k_scatter_edges<<<(N_EDGES + 255) / 256, 256>>>(edge);

    // conditioning embedding
    k_cond<<<(N_NODES + 127) / 128, 128>>>(noise, f_w1, f_b1, f_w2, f_b2);

    dim3 ggrid(4, (N_NODES + 127) / 128);
    for (int b = 0; b < NB; b++) {
        const size_t wOff = (size_t)b * DIM * DIM;
        const size_t bOff = (size_t)b * DIM;
        const size_t cOff = (size_t)b * CDIM * DIM;

        // CLN1 -> g_y
        k_cln<<<N_NODES, 128>>>(x, s1_w + cOff, s1_b + bOff, b1_w + cOff, b1_b + bOff);
        // QKV projections
        k_gemm512<<<ggrid, 256>>>(yp, wq + wOff, bq + bOff, nullptr, qp, N_NODES, 0);
        k_gemm512<<<ggrid, 256>>>(yp, wk + wOff, bk + bOff, nullptr, kp, N_NODES, 0);
        k_gemm512<<<ggrid, 256>>>(yp, wv + wOff, bv + bOff, nullptr, vp, N_NODES, 0);
        // sparse attention -> g_attn
        k_attn<<<N_NODES, 128>>>();
        // output projection + residual -> x
        k_gemm512<<<ggrid, 256>>>(ap, wo + wOff, bo + bOff, x, x, N_NODES, 2);
        // CLN2 -> g_y
        k_cln<<<N_NODES, 128>>>(x, s2_w + cOff, s2_b + bOff, b2_w + cOff, b2_b + bOff);
        // MLP
        k_gemm512<<<ggrid, 256>>>(yp, m_w1 + wOff, m_b1 + bOff, nullptr, hp, N_NODES, 1);
        k_gemm512<<<ggrid, 256>>>(hp, m_w2 + wOff, m_b2 + bOff, x, x, N_NODES, 2);
    }
}

// round 4
// speedup vs baseline: 2.7145x; 2.7145x over previous
#include <cuda_runtime.h>
#include <cuda_fp16.h>
#include <math.h>
#include <stdint.h>

#define N_NODES 40962
#define DIM 512
#define N_EDGES 655392
#define NB 4
#define NHEADS 4
#define DH 128
#define CDIM 16
#define NFREQ 32

// ---------------- scratch (device globals; no allocation allowed) ----------------
__device__ float g_q[(size_t)N_NODES * DIM];
__device__ float g_k[(size_t)N_NODES * DIM];
__device__ float g_v[(size_t)N_NODES * DIM];
__device__ __half g_y16[(size_t)N_NODES * DIM];
__device__ __half g_attn16[(size_t)N_NODES * DIM];
__device__ __half g_h16[(size_t)N_NODES * DIM];
__device__ float g_cond[(size_t)N_NODES * CDIM];
__device__ int g_deg[N_NODES];
__device__ int g_rowptr[N_NODES + 1];
__device__ int g_cursor[N_NODES];
__device__ int g_csrdst[N_EDGES];
// weights transposed to [N,K] fp16.  24 slots = 4 blocks x {q,k,v,o,m1,m2}
__device__ __half g_wt[24ull * 512 * 512];

// ---------------- helpers ----------------
__device__ __forceinline__ uint32_t smem_u32(const void* p) {
    uint32_t a;
    asm("{ .reg .u64 t; cvta.to.shared.u64 t, %1; cvt.u32.u64 %0, t; }"
        : "=r"(a) : "l"(p));
    return a;
}

#define LDSM4(r, addr) \
    asm volatile("ldmatrix.sync.aligned.m8n8.x4.shared.b16 {%0,%1,%2,%3}, [%4];" \
        : "=r"((r)[0]), "=r"((r)[1]), "=r"((r)[2]), "=r"((r)[3]) : "r"(addr))

#define MMA16816(d, a, b0, b1) \
    asm volatile("mma.sync.aligned.m16n8k16.row.col.f32.f16.f16.f32 " \
        "{%0,%1,%2,%3}, {%4,%5,%6,%7}, {%8,%9}, {%0,%1,%2,%3};" \
        : "+f"((d)[0]), "+f"((d)[1]), "+f"((d)[2]), "+f"((d)[3]) \
        : "r"((a)[0]), "r"((a)[1]), "r"((a)[2]), "r"((a)[3]), "r"(b0), "r"(b1))

#define CP_ASYNC16(dst, src, sz) \
    asm volatile("cp.async.cg.shared.global [%0], [%1], 16, %2;" \
        :: "r"(dst), "l"(src), "r"(sz) : "memory")
#define CP_COMMIT() asm volatile("cp.async.commit_group;" ::: "memory")
#define CP_WAIT(N)  asm volatile("cp.async.wait_group %0;" :: "n"(N) : "memory")

// ---------------- CSR build ----------------
__global__ void k_zero_deg() {
    int i = blockIdx.x * blockDim.x + threadIdx.x;
    if (i < N_NODES) g_deg[i] = 0;
}

__global__ void k_count_deg(const int* __restrict__ edge) {
    int e = blockIdx.x * blockDim.x + threadIdx.x;
    if (e < N_EDGES) atomicAdd(&g_deg[edge[e]], 1);
}

__global__ void k_scan_deg() {
    __shared__ int partial[1024];
    const int tid = threadIdx.x;
    const int CH = (N_NODES + 1023) / 1024;
    const int base = tid * CH;
    int sum = 0;
    for (int i = 0; i < CH; i++) {
        int idx = base + i;
        if (idx < N_NODES) sum += g_deg[idx];
    }
    partial[tid] = sum;
    __syncthreads();
    for (int off = 1; off < 1024; off <<= 1) {
        int t = (tid >= off) ? partial[tid - off] : 0;
        __syncthreads();
        partial[tid] += t;
        __syncthreads();
    }
    int offset = (tid > 0) ? partial[tid - 1] : 0;
    for (int i = 0; i < CH; i++) {
        int idx = base + i;
        if (idx < N_NODES) {
            g_rowptr[idx] = offset;
            g_cursor[idx] = offset;
            offset += g_deg[idx];
        }
    }
    if (tid == 1023) g_rowptr[N_NODES] = partial[1023];
}

__global__ void k_scatter_edges(const int* __restrict__ edge) {
    int e = blockIdx.x * blockDim.x + threadIdx.x;
    if (e < N_EDGES) {
        int s = edge[e];
        int d = edge[N_EDGES + e];
        int p = atomicAdd(&g_cursor[s], 1);
        g_csrdst[p] = d;
    }
}

// ---------------- weight prep: transpose fp32 W[K,N] -> fp16 WT[N,K] ----------------
__global__ void k_prep_w(const float* __restrict__ wq, const float* __restrict__ wk,
                         const float* __restrict__ wv, const float* __restrict__ wo,
                         const float* __restrict__ w1, const float* __restrict__ w2) {
    int slot = blockIdx.z;
    int b = slot / 6, t = slot % 6;
    const float* W =
        (t == 0 ? wq : t == 1 ? wk : t == 2 ? wv : t == 3 ? wo : t == 4 ? w1 : w2) +
        (size_t)b * 512 * 512;
    __shared__ float tile[32][33];
    int x0 = blockIdx.x * 32, y0 = blockIdx.y * 32;
    int tx = threadIdx.x, ty = threadIdx.y;
    #pragma unroll
    for (int r = 0; r < 32; r += 8)
        tile[ty + r][tx] = W[(size_t)(y0 + ty + r) * 512 + x0 + tx];
    __syncthreads();
    size_t base = (size_t)slot * 512 * 512;
    #pragma unroll
    for (int r = 0; r < 32; r += 8) {
        float v = tile[tx][ty + r];
        g_wt[base + (size_t)(x0 + ty + r) * 512 + y0 + tx] = __float2half_rn(v);
    }
}

// ---------------- Fourier noise embedding + cond MLP ----------------
__global__ void k_cond(const float* __restrict__ noise,
                       const float* __restrict__ fw1, const float* __restrict__ fb1,
                       const float* __restrict__ fw2, const float* __restrict__ fb2) {
    __shared__ float s_w1[2 * NFREQ * CDIM];
    __shared__ float s_w2[CDIM * CDIM];
    __shared__ float s_b1[CDIM];
    __shared__ float s_b2[CDIM];
    for (int i = threadIdx.x; i < 2 * NFREQ * CDIM; i += blockDim.x) s_w1[i] = fw1[i];
    for (int i = threadIdx.x; i < CDIM * CDIM; i += blockDim.x) s_w2[i] = fw2[i];
    if (threadIdx.x < CDIM) {
        s_b1[threadIdx.x] = fb1[threadIdx.x];
        s_b2[threadIdx.x] = fb2[threadIdx.x];
    }
    __syncthreads();
    int n = blockIdx.x * blockDim.x + threadIdx.x;
    if (n >= N_NODES) return;
    float t = noise[n];
    const float w0 = 2.0f * 3.14159265358979323846f / 16.0f;
    float emb[2 * NFREQ];
    #pragma unroll
    for (int f = 0; f < NFREQ; f++) {
        float ph = t * (w0 * (float)(f + 1));
        emb[f] = sinf(ph);
        emb[NFREQ + f] = cosf(ph);
    }
    float h[CDIM];
    #pragma unroll
    for (int c = 0; c < CDIM; c++) {
        float acc = s_b1[c];
        #pragma unroll
        for (int f = 0; f < 2 * NFREQ; f++) acc = fmaf(emb[f], s_w1[f * CDIM + c], acc);
        h[c] = acc / (1.0f + expf(-acc));
    }
    #pragma unroll
    for (int c2 = 0; c2 < CDIM; c2++) {
        float acc = s_b2[c2];
        #pragma unroll
        for (int c = 0; c < CDIM; c++) acc = fmaf(h[c], s_w2[c * CDIM + c2], acc);
        g_cond[n * CDIM + c2] = acc;
    }
}

// ---------------- conditional LayerNorm (FiLM) -> fp16 output ----------------
__global__ void k_cln(const float* __restrict__ x,
                      const float* __restrict__ sw, const float* __restrict__ sb,
                      const float* __restrict__ bw, const float* __restrict__ bb) {
    int n = blockIdx.x;
    int tid = threadIdx.x;
    __shared__ float s_cond[CDIM];
    __shared__ float s_red[8];
    if (tid < CDIM) s_cond[tid] = g_cond[n * CDIM + tid];
    float4 xv = *(const float4*)(x + (size_t)n * DIM + tid * 4);
    float s = xv.x + xv.y + xv.z + xv.w;
    float s2 = fmaf(xv.x, xv.x, fmaf(xv.y, xv.y, fmaf(xv.z, xv.z, xv.w * xv.w)));
    #pragma unroll
    for (int o = 16; o; o >>= 1) {
        s += __shfl_xor_sync(0xffffffffu, s, o);
        s2 += __shfl_xor_sync(0xffffffffu, s2, o);
    }
    int w = tid >> 5, l = tid & 31;
    if (l == 0) { s_red[w] = s; s_red[4 + w] = s2; }
    __syncthreads();
    s = s_red[0] + s_red[1] + s_red[2] + s_red[3];
    s2 = s_red[4] + s_red[5] + s_red[6] + s_red[7];
    float mu = s * (1.0f / DIM);
    float var = s2 * (1.0f / DIM) - mu * mu;
    float inv = rsqrtf(var + 1e-5f);
    int d0 = tid * 4;
    float sc[4], bi[4];
    #pragma unroll
    for (int j = 0; j < 4; j++) { sc[j] = sb[d0 + j]; bi[j] = bb[d0 + j]; }
    #pragma unroll
    for (int c = 0; c < CDIM; c++) {
        float cv = s_cond[c];
        const float* swr = sw + c * DIM + d0;
        const float* bwr = bw + c * DIM + d0;
        #pragma unroll
        for (int j = 0; j < 4; j++) {
            sc[j] = fmaf(cv, swr[j], sc[j]);
            bi[j] = fmaf(cv, bwr[j], bi[j]);
        }
    }
    float o0 = (xv.x - mu) * inv * (1.0f + sc[0]) + bi[0];
    float o1 = (xv.y - mu) * inv * (1.0f + sc[1]) + bi[1];
    float o2 = (xv.z - mu) * inv * (1.0f + sc[2]) + bi[2];
    float o3 = (xv.w - mu) * inv * (1.0f + sc[3]) + bi[3];
    __half2 h01 = __floats2half2_rn(o0, o1);
    __half2 h23 = __floats2half2_rn(o2, o3);
    *(uint2*)(g_y16 + (size_t)n * DIM + d0) =
        make_uint2(*(uint32_t*)&h01, *(uint32_t*)&h23);
}

// ---------------- HMMA GEMM: C[M,512] = A[M,512](fp16) @ WT^T + bias ----------------
// WT is [N,K] fp16. 128x128x32 tiles, 256 thr, 8 warps (2x4), warp tile 64x32.
// flags: bit0 relu, bit1 residual(+Res fp32), bit2 fp16 out (to Ch)
#define PITCH 40  // halves per smem row (80B: conflict-free ldmatrix)

__device__ __forceinline__ void g_load_tiles(
    const __half* __restrict__ A, const __half* __restrict__ WT,
    uint32_t sa, uint32_t sbm, int row0, int k0, int M, int tid) {
    #pragma unroll
    for (int i = 0; i < 2; i++) {
        int v = i * 256 + tid;
        int r = v >> 2, q = v & 3;
        uint32_t dst = sa + (uint32_t)(r * (PITCH * 2) + q * 16);
        const __half* src = A + (size_t)(row0 + r) * 512 + k0 + q * 8;
        int sz = (row0 + r < M) ? 16 : 0;
        CP_ASYNC16(dst, src, sz);
    }
    #pragma unroll
    for (int i = 0; i < 2; i++) {
        int v = i * 256 + tid;
        int r = v >> 2, q = v & 3;
        uint32_t dst = sbm + (uint32_t)(r * (PITCH * 2) + q * 16);
        const __half* src = WT + (size_t)r * 512 + k0 + q * 8;
        CP_ASYNC16(dst, src, 16);
    }
    CP_COMMIT();
}

__global__ __launch_bounds__(256) void k_gemm_hmma(
    const __half* __restrict__ A, int slot,
    const float* __restrict__ Bias, const float* __restrict__ Res,
    float* __restrict__ C, __half* __restrict__ Ch, int M, int flags) {
    __shared__ __half sA[2][128 * PITCH];
    __shared__ __half sB[2][128 * PITCH];
    const int tid = threadIdx.x;
    const int lane = tid & 31, wid = tid >> 5;
    const int warpM = wid >> 2, warpN = wid & 3;   // 2 x 4
    const int col0 = blockIdx.x * 128, row0 = blockIdx.y * 128;
    const __half* WT = g_wt + (size_t)slot * 512 * 512 + (size_t)col0 * 512;

    const uint32_t saBase = smem_u32(sA);
    const uint32_t sbBase = smem_u32(sB);

    float acc[4][4][4];
    #pragma unroll
    for (int i = 0; i < 4; i++)
        #pragma unroll
        for (int j = 0; j < 4; j++)
            #pragma unroll
            for (int r = 0; r < 4; r++) acc[i][j][r] = 0.0f;

    g_load_tiles(A, WT, saBase, sbBase, row0, 0, M, tid);

    const int aRow = lane & 15, aHi = lane >> 4;
    #pragma unroll 1
    for (int c = 0; c < 16; c++) {
        int buf = c & 1;
        if (c < 15)
            g_load_tiles(A, WT, saBase + (buf ^ 1) * 128 * PITCH * 2,
                         sbBase + (buf ^ 1) * 128 * PITCH * 2, row0,
                         (c + 1) * 32, M, tid);
        if (c < 15) { CP_WAIT(1); } else { CP_WAIT(0); }
        __syncthreads();

        uint32_t aB = saBase + buf * 128 * PITCH * 2;
        uint32_t bB = sbBase + buf * 128 * PITCH * 2;
        #pragma unroll
        for (int ks = 0; ks < 2; ks++) {
            uint32_t ra[4][4], rb[2][4];
            #pragma unroll
            for (int mt = 0; mt < 4; mt++) {
                uint32_t addr = aB +
                    (uint32_t)((warpM * 64 + mt * 16 + aRow) * (PITCH * 2) +
                               ks * 32 + aHi * 16);
                LDSM4(ra[mt], addr);
            }
            #pragma unroll
            for (int bt = 0; bt < 2; bt++) {
                uint32_t addr = bB +
                    (uint32_t)((warpN * 32 + bt * 16 + aRow) * (PITCH * 2) +
                               ks * 32 + aHi * 16);
                LDSM4(rb[bt], addr);   // B stored [n][k]: non-trans gives k-pairs per n
            }
            #pragma unroll
            for (int mt = 0; mt < 4; mt++) {
                #pragma unroll
                for (int bt = 0; bt < 2; bt++) {
                    MMA16816(acc[mt][bt * 2 + 0], ra[mt], rb[bt][0], rb[bt][2]);
                    MMA16816(acc[mt][bt * 2 + 1], ra[mt], rb[bt][1], rb[bt][3]);
                }
            }
        }
        __syncthreads();
    }

    // epilogue
    const bool relu = (flags & 1) != 0;
    const bool resid = (flags & 2) != 0;
    const bool half_out = (flags & 4) != 0;
    #pragma unroll
    for (int mt = 0; mt < 4; mt++) {
        #pragma unroll
        for (int nt = 0; nt < 4; nt++) {
            int gr = row0 + warpM * 64 + mt * 16 + (lane >> 2);
            int gc = col0 + warpN * 32 + (nt >> 1) * 16 + (nt & 1) * 8 +
                     (lane & 3) * 2;
            float2 b2 = *(const float2*)(Bias + gc);
            #pragma unroll
            for (int h = 0; h < 2; h++) {
                int row = gr + h * 8;
                if (row >= M) continue;
                float v0 = acc[mt][nt][h * 2 + 0] + b2.x;
                float v1 = acc[mt][nt][h * 2 + 1] + b2.y;
                if (relu) { v0 = fmaxf(v0, 0.f); v1 = fmaxf(v1, 0.f); }
                if (resid) {
                    float2 rv = *(const float2*)(Res + (size_t)row * 512 + gc);
                    v0 += rv.x; v1 += rv.y;
                }
                if (half_out) {
                    __half2 hv = __floats2half2_rn(v0, v1);
                    *(__half2*)(Ch + (size_t)row * 512 + gc) = hv;
                } else {
                    *(float2*)(C + (size_t)row * 512 + gc) = make_float2(v0, v1);
                }
            }
        }
    }
}

// ---------------- sparse attention: one block per node, one warp per head ----------
__global__ void k_attn() {
    int n = blockIdx.x;
    int warp = threadIdx.x >> 5;
    int lane = threadIdx.x & 31;
    int beg = g_rowptr[n], end = g_rowptr[n + 1];
    const float scale = 0.08838834764831845f;
    size_t base = (size_t)n * DIM + warp * DH + lane * 4;
    float4 qv = *(const float4*)&g_q[base];
    float m = -INFINITY, s = 0.0f;
    float a0 = 0.f, a1 = 0.f, a2 = 0.f, a3 = 0.f;
    for (int e = beg; e < end; e++) {
        int d = g_csrdst[e];
        size_t kb = (size_t)d * DIM + warp * DH + lane * 4;
        float4 kv = *(const float4*)&g_k[kb];
        float p = qv.x * kv.x + qv.y * kv.y + qv.z * kv.z + qv.w * kv.w;
        p += __shfl_xor_sync(0xffffffffu, p, 16);
        p += __shfl_xor_sync(0xffffffffu, p, 8);
        p += __shfl_xor_sync(0xffffffffu, p, 4);
        p += __shfl_xor_sync(0xffffffffu, p, 2);
        p += __shfl_xor_sync(0xffffffffu, p, 1);
        float score = p * scale;
        float4 vv = *(const float4*)&g_v[kb];
        float mn = fmaxf(m, score);
        float corr = expf(m - mn);
        float w = expf(score - mn);
        s = s * corr + w;
        a0 = fmaf(w, vv.x, a0 * corr);
        a1 = fmaf(w, vv.y, a1 * corr);
        a2 = fmaf(w, vv.z, a2 * corr);
        a3 = fmaf(w, vv.w, a3 * corr);
        m = mn;
    }
    float inv = (end > beg) ? (1.0f / s) : 0.0f;
    __half2 h01 = __floats2half2_rn(a0 * inv, a1 * inv);
    __half2 h23 = __floats2half2_rn(a2 * inv, a3 * inv);
    *(uint2*)(g_attn16 + base) = make_uint2(*(uint32_t*)&h01, *(uint32_t*)&h23);
}

// ---------------- host ----------------
extern "C" void kernel_launch(void* const* d_in, const int* in_sizes, int n_in,
                              void* d_out, int out_size) {
    const float* x_in  = (const float*)d_in[0];
    const int*   edge  = (const int*)d_in[1];
    const float* noise = (const float*)d_in[2];
    const float* f_w1 = (const float*)d_in[3];
    const float* f_b1 = (const float*)d_in[4];
    const float* f_w2 = (const float*)d_in[5];
    const float* f_b2 = (const float*)d_in[6];
    const float* s1_w = (const float*)d_in[7];
    const float* s1_b = (const float*)d_in[8];
    const float* b1_w = (const float*)d_in[9];
    const float* b1_b = (const float*)d_in[10];
    const float* wq = (const float*)d_in[11];
    const float* bq = (const float*)d_in[12];
    const float* wk = (const float*)d_in[13];
    const float* bk = (const float*)d_in[14];
    const float* wv = (const float*)d_in[15];
    const float* bv = (const float*)d_in[16];
    const float* wo = (const float*)d_in[17];
    const float* bo = (const float*)d_in[18];
    const float* s2_w = (const float*)d_in[19];
    const float* s2_b = (const float*)d_in[20];
    const float* b2_w = (const float*)d_in[21];
    const float* b2_b = (const float*)d_in[22];
    const float* m_w1 = (const float*)d_in[23];
    const float* m_b1 = (const float*)d_in[24];
    const float* m_w2 = (const float*)d_in[25];
    const float* m_b2 = (const float*)d_in[26];

    float* x = (float*)d_out;

    float *qp, *kp, *vp;
    __half *yp16, *ap16, *hp16;
    cudaGetSymbolAddress((void**)&qp, g_q);
    cudaGetSymbolAddress((void**)&kp, g_k);
    cudaGetSymbolAddress((void**)&vp, g_v);
    cudaGetSymbolAddress((void**)&yp16, g_y16);
    cudaGetSymbolAddress((void**)&ap16, g_attn16);
    cudaGetSymbolAddress((void**)&hp16, g_h16);

    cudaMemcpyAsync(x, x_in, (size_t)N_NODES * DIM * sizeof(float),
                    cudaMemcpyDeviceToDevice);

    // CSR build
    k_zero_deg<<<(N_NODES + 255) / 256, 256>>>();
    k_count_deg<<<(N_EDGES + 255) / 256, 256>>>(edge);
    k_scan_deg<<<1, 1024>>>();
    k_scatter_edges<<<(N_EDGES + 255) / 256, 256>>>(edge);

    // weight prep + conditioning
    k_prep_w<<<dim3(16, 16, 24), dim3(32, 8)>>>(wq, wk, wv, wo, m_w1, m_w2);
    k_cond<<<(N_NODES + 127) / 128, 128>>>(noise, f_w1, f_b1, f_w2, f_b2);

    dim3 ggrid(4, (N_NODES + 127) / 128);
    for (int b = 0; b < NB; b++) {
        const size_t bOff = (size_t)b * DIM;
        const size_t cOff = (size_t)b * CDIM * DIM;
        const int slot = b * 6;

        k_cln<<<N_NODES, 128>>>(x, s1_w + cOff, s1_b + bOff, b1_w + cOff, b1_b + bOff);
        k_gemm_hmma<<<ggrid, 256>>>(yp16, slot + 0, bq + bOff, nullptr, qp, nullptr, N_NODES, 0);
        k_gemm_hmma<<<ggrid, 256>>>(yp16, slot + 1, bk + bOff, nullptr, kp, nullptr, N_NODES, 0);
        k_gemm_hmma<<<ggrid, 256>>>(yp16, slot + 2, bv + bOff, nullptr, vp, nullptr, N_NODES, 0);
        k_attn<<<N_NODES, 128>>>();
        k_gemm_hmma<<<ggrid, 256>>>(ap16, slot + 3, bo + bOff, x, x, nullptr, N_NODES, 2);
        k_cln<<<N_NODES, 128>>>(x, s2_w + cOff, s2_b + bOff, b2_w + cOff, b2_b + bOff);
        k_gemm_hmma<<<ggrid, 256>>>(yp16, slot + 4, m_b1 + bOff, nullptr, nullptr, hp16, N_NODES, 5);
        k_gemm_hmma<<<ggrid, 256>>>(hp16, slot + 5, m_b2 + bOff, x, x, nullptr, N_NODES, 2);
    }
}

// round 5
// speedup vs baseline: 2.9772x; 1.0968x over previous
#include <cuda_runtime.h>
#include <cuda_fp16.h>
#include <math.h>
#include <stdint.h>

#define N_NODES 40962
#define DIM 512
#define N_EDGES 655392
#define NB 4
#define NHEADS 4
#define DH 128
#define CDIM 16
#define NFREQ 32

// ---------------- scratch (device globals; no allocation allowed) ----------------
__device__ __half g_q16[(size_t)N_NODES * DIM];
__device__ __half g_k16[(size_t)N_NODES * DIM];
__device__ __half g_v16[(size_t)N_NODES * DIM];
__device__ __half g_y16[(size_t)N_NODES * DIM];
__device__ __half g_attn16[(size_t)N_NODES * DIM];
__device__ __half g_h16[(size_t)N_NODES * DIM];
__device__ float g_cond[(size_t)N_NODES * CDIM];
__device__ int g_deg[N_NODES];
__device__ int g_rowptr[N_NODES + 1];
__device__ int g_cursor[N_NODES];
__device__ int g_csrdst[N_EDGES];
// weights transposed to [N,K] fp16.  24 slots = 4 blocks x {q,k,v,o,m1,m2}
__device__ __half g_wt[24ull * 512 * 512];

// ---------------- helpers ----------------
__device__ __forceinline__ uint32_t smem_u32(const void* p) {
    uint32_t a;
    asm("{ .reg .u64 t; cvta.to.shared.u64 t, %1; cvt.u32.u64 %0, t; }"
        : "=r"(a) : "l"(p));
    return a;
}

#define LDSM4(r, addr) \
    asm volatile("ldmatrix.sync.aligned.m8n8.x4.shared.b16 {%0,%1,%2,%3}, [%4];" \
        : "=r"((r)[0]), "=r"((r)[1]), "=r"((r)[2]), "=r"((r)[3]) : "r"(addr))

#define MMA16816(d, a, b0, b1) \
    asm volatile("mma.sync.aligned.m16n8k16.row.col.f32.f16.f16.f32 " \
        "{%0,%1,%2,%3}, {%4,%5,%6,%7}, {%8,%9}, {%0,%1,%2,%3};" \
        : "+f"((d)[0]), "+f"((d)[1]), "+f"((d)[2]), "+f"((d)[3]) \
        : "r"((a)[0]), "r"((a)[1]), "r"((a)[2]), "r"((a)[3]), "r"(b0), "r"(b1))

#define CP_ASYNC16(dst, src, sz) \
    asm volatile("cp.async.cg.shared.global [%0], [%1], 16, %2;" \
        :: "r"(dst), "l"(src), "r"(sz) : "memory")
#define CP_COMMIT() asm volatile("cp.async.commit_group;" ::: "memory")
#define CP_WAIT(N)  asm volatile("cp.async.wait_group %0;" :: "n"(N) : "memory")

// ---------------- CSR build ----------------
__global__ void k_zero_deg() {
    int i = blockIdx.x * blockDim.x + threadIdx.x;
    if (i < N_NODES) g_deg[i] = 0;
}

__global__ void k_count_deg(const int* __restrict__ edge) {
    int e = blockIdx.x * blockDim.x + threadIdx.x;
    if (e < N_EDGES) atomicAdd(&g_deg[edge[e]], 1);
}

__global__ void k_scan_deg() {
    __shared__ int partial[1024];
    const int tid = threadIdx.x;
    const int CH = (N_NODES + 1023) / 1024;
    const int base = tid * CH;
    int sum = 0;
    for (int i = 0; i < CH; i++) {
        int idx = base + i;
        if (idx < N_NODES) sum += g_deg[idx];
    }
    partial[tid] = sum;
    __syncthreads();
    for (int off = 1; off < 1024; off <<= 1) {
        int t = (tid >= off) ? partial[tid - off] : 0;
        __syncthreads();
        partial[tid] += t;
        __syncthreads();
    }
    int offset = (tid > 0) ? partial[tid - 1] : 0;
    for (int i = 0; i < CH; i++) {
        int idx = base + i;
        if (idx < N_NODES) {
            g_rowptr[idx] = offset;
            g_cursor[idx] = offset;
            offset += g_deg[idx];
        }
    }
    if (tid == 1023) g_rowptr[N_NODES] = partial[1023];
}

__global__ void k_scatter_edges(const int* __restrict__ edge) {
    int e = blockIdx.x * blockDim.x + threadIdx.x;
    if (e < N_EDGES) {
        int s = edge[e];
        int d = edge[N_EDGES + e];
        int p = atomicAdd(&g_cursor[s], 1);
        g_csrdst[p] = d;
    }
}

// ---------------- weight prep: transpose fp32 W[K,N] -> fp16 WT[N,K] ----------------
__global__ void k_prep_w(const float* __restrict__ wq, const float* __restrict__ wk,
                         const float* __restrict__ wv, const float* __restrict__ wo,
                         const float* __restrict__ w1, const float* __restrict__ w2) {
    int slot = blockIdx.z;
    int b = slot / 6, t = slot % 6;
    const float* W =
        (t == 0 ? wq : t == 1 ? wk : t == 2 ? wv : t == 3 ? wo : t == 4 ? w1 : w2) +
        (size_t)b * 512 * 512;
    __shared__ float tile[32][33];
    int x0 = blockIdx.x * 32, y0 = blockIdx.y * 32;
    int tx = threadIdx.x, ty = threadIdx.y;
    #pragma unroll
    for (int r = 0; r < 32; r += 8)
        tile[ty + r][tx] = W[(size_t)(y0 + ty + r) * 512 + x0 + tx];
    __syncthreads();
    size_t base = (size_t)slot * 512 * 512;
    #pragma unroll
    for (int r = 0; r < 32; r += 8) {
        float v = tile[tx][ty + r];
        g_wt[base + (size_t)(x0 + ty + r) * 512 + y0 + tx] = __float2half_rn(v);
    }
}

// ---------------- Fourier noise embedding + cond MLP ----------------
__global__ void k_cond(const float* __restrict__ noise,
                       const float* __restrict__ fw1, const float* __restrict__ fb1,
                       const float* __restrict__ fw2, const float* __restrict__ fb2) {
    __shared__ float s_w1[2 * NFREQ * CDIM];
    __shared__ float s_w2[CDIM * CDIM];
    __shared__ float s_b1[CDIM];
    __shared__ float s_b2[CDIM];
    for (int i = threadIdx.x; i < 2 * NFREQ * CDIM; i += blockDim.x) s_w1[i] = fw1[i];
    for (int i = threadIdx.x; i < CDIM * CDIM; i += blockDim.x) s_w2[i] = fw2[i];
    if (threadIdx.x < CDIM) {
        s_b1[threadIdx.x] = fb1[threadIdx.x];
        s_b2[threadIdx.x] = fb2[threadIdx.x];
    }
    __syncthreads();
    int n = blockIdx.x * blockDim.x + threadIdx.x;
    if (n >= N_NODES) return;
    float t = noise[n];
    const float w0 = 2.0f * 3.14159265358979323846f / 16.0f;
    float emb[2 * NFREQ];
    #pragma unroll
    for (int f = 0; f < NFREQ; f++) {
        float ph = t * (w0 * (float)(f + 1));
        emb[f] = sinf(ph);
        emb[NFREQ + f] = cosf(ph);
    }
    float h[CDIM];
    #pragma unroll
    for (int c = 0; c < CDIM; c++) {
        float acc = s_b1[c];
        #pragma unroll
        for (int f = 0; f < 2 * NFREQ; f++) acc = fmaf(emb[f], s_w1[f * CDIM + c], acc);
        h[c] = acc / (1.0f + expf(-acc));
    }
    #pragma unroll
    for (int c2 = 0; c2 < CDIM; c2++) {
        float acc = s_b2[c2];
        #pragma unroll
        for (int c = 0; c < CDIM; c++) acc = fmaf(h[c], s_w2[c * CDIM + c2], acc);
        g_cond[n * CDIM + c2] = acc;
    }
}

// ---------------- conditional LayerNorm (FiLM) -> fp16 output ----------------
__global__ void k_cln(const float* __restrict__ x,
                      const float* __restrict__ sw, const float* __restrict__ sb,
                      const float* __restrict__ bw, const float* __restrict__ bb) {
    int n = blockIdx.x;
    int tid = threadIdx.x;
    __shared__ float s_cond[CDIM];
    __shared__ float s_red[8];
    if (tid < CDIM) s_cond[tid] = g_cond[n * CDIM + tid];
    float4 xv = *(const float4*)(x + (size_t)n * DIM + tid * 4);
    float s = xv.x + xv.y + xv.z + xv.w;
    float s2 = fmaf(xv.x, xv.x, fmaf(xv.y, xv.y, fmaf(xv.z, xv.z, xv.w * xv.w)));
    #pragma unroll
    for (int o = 16; o; o >>= 1) {
        s += __shfl_xor_sync(0xffffffffu, s, o);
        s2 += __shfl_xor_sync(0xffffffffu, s2, o);
    }
    int w = tid >> 5, l = tid & 31;
    if (l == 0) { s_red[w] = s; s_red[4 + w] = s2; }
    __syncthreads();
    s = s_red[0] + s_red[1] + s_red[2] + s_red[3];
    s2 = s_red[4] + s_red[5] + s_red[6] + s_red[7];
    float mu = s * (1.0f / DIM);
    float var = s2 * (1.0f / DIM) - mu * mu;
    float inv = rsqrtf(var + 1e-5f);
    int d0 = tid * 4;
    float sc[4], bi[4];
    #pragma unroll
    for (int j = 0; j < 4; j++) { sc[j] = sb[d0 + j]; bi[j] = bb[d0 + j]; }
    #pragma unroll
    for (int c = 0; c < CDIM; c++) {
        float cv = s_cond[c];
        const float* swr = sw + c * DIM + d0;
        const float* bwr = bw + c * DIM + d0;
        #pragma unroll
        for (int j = 0; j < 4; j++) {
            sc[j] = fmaf(cv, swr[j], sc[j]);
            bi[j] = fmaf(cv, bwr[j], bi[j]);
        }
    }
    float o0 = (xv.x - mu) * inv * (1.0f + sc[0]) + bi[0];
    float o1 = (xv.y - mu) * inv * (1.0f + sc[1]) + bi[1];
    float o2 = (xv.z - mu) * inv * (1.0f + sc[2]) + bi[2];
    float o3 = (xv.w - mu) * inv * (1.0f + sc[3]) + bi[3];
    __half2 h01 = __floats2half2_rn(o0, o1);
    __half2 h23 = __floats2half2_rn(o2, o3);
    *(uint2*)(g_y16 + (size_t)n * DIM + d0) =
        make_uint2(*(uint32_t*)&h01, *(uint32_t*)&h23);
}

// ---------------- HMMA GEMM: 128x128x64 tiles, 3-stage cp.async pipeline ----------
// WT [N,K] fp16.  256 thr, 8 warps (2x4), warp tile 64x32.
// flags: bit0 relu, bit1 residual(+Res fp32), bit2 fp16 out (to Ch)
#define SPITCH 72                       // halves per smem row (144B, conflict-free LDSM)
#define AB_OFF (128 * SPITCH * 2)       // B tile offset within stage (bytes)
#define STAGE_BYTES (256 * SPITCH * 2)  // 36864 B
#define NSTAGE 3
#define GEMM_SMEM (NSTAGE * STAGE_BYTES)

__device__ __forceinline__ void g_load_stage(
    const __half* __restrict__ A, const __half* __restrict__ WT,
    uint32_t sbase, int row0, int k0, int M, int tid) {
    // A: 128 rows x 64 halves (8 chunks of 16B per row)
    #pragma unroll
    for (int i = 0; i < 4; i++) {
        int v = i * 256 + tid;
        int r = v >> 3, q = v & 7;
        uint32_t dst = sbase + (uint32_t)(r * (SPITCH * 2) + q * 16);
        const __half* src = A + (size_t)(row0 + r) * 512 + k0 + q * 8;
        int sz = (row0 + r < M) ? 16 : 0;
        CP_ASYNC16(dst, src, sz);
    }
    // B: 128 rows x 64 halves
    #pragma unroll
    for (int i = 0; i < 4; i++) {
        int v = i * 256 + tid;
        int r = v >> 3, q = v & 7;
        uint32_t dst = sbase + AB_OFF + (uint32_t)(r * (SPITCH * 2) + q * 16);
        const __half* src = WT + (size_t)r * 512 + k0 + q * 8;
        CP_ASYNC16(dst, src, 16);
    }
    CP_COMMIT();
}

__global__ __launch_bounds__(256) void k_gemm_hmma(
    const __half* __restrict__ A, int slot,
    const float* __restrict__ Bias, const float* __restrict__ Res,
    float* __restrict__ C, __half* __restrict__ Ch, int M, int flags) {
    extern __shared__ __align__(128) char smem[];
    const int tid = threadIdx.x;
    const int lane = tid & 31, wid = tid >> 5;
    const int warpM = wid >> 2, warpN = wid & 3;   // 2 x 4
    const int col0 = blockIdx.x * 128, row0 = blockIdx.y * 128;
    const __half* WT = g_wt + (size_t)slot * 512 * 512 + (size_t)col0 * 512;
    const uint32_t sb = smem_u32(smem);

    float acc[4][4][4];
    #pragma unroll
    for (int i = 0; i < 4; i++)
        #pragma unroll
        for (int j = 0; j < 4; j++)
            #pragma unroll
            for (int r = 0; r < 4; r++) acc[i][j][r] = 0.0f;

    g_load_stage(A, WT, sb, row0, 0, M, tid);
    g_load_stage(A, WT, sb + STAGE_BYTES, row0, 64, M, tid);

    const int aRow = lane & 15, aHi = lane >> 4;
    #pragma unroll 1
    for (int it = 0; it < 8; it++) {
        if (it < 7) { CP_WAIT(1); } else { CP_WAIT(0); }
        __syncthreads();
        if (it < 6)
            g_load_stage(A, WT, sb + (uint32_t)((it + 2) % NSTAGE) * STAGE_BYTES,
                         row0, (it + 2) * 64, M, tid);

        uint32_t aB = sb + (uint32_t)(it % NSTAGE) * STAGE_BYTES;
        uint32_t bB = aB + AB_OFF;
        #pragma unroll
        for (int ks = 0; ks < 4; ks++) {
            uint32_t ra[4][4], rb[2][4];
            #pragma unroll
            for (int mt = 0; mt < 4; mt++) {
                uint32_t addr = aB +
                    (uint32_t)((warpM * 64 + mt * 16 + aRow) * (SPITCH * 2) +
                               ks * 32 + aHi * 16);
                LDSM4(ra[mt], addr);
            }
            #pragma unroll
            for (int bt = 0; bt < 2; bt++) {
                uint32_t addr = bB +
                    (uint32_t)((warpN * 32 + bt * 16 + aRow) * (SPITCH * 2) +
                               ks * 32 + aHi * 16);
                LDSM4(rb[bt], addr);   // B stored [n][k]: non-trans gives k-pairs per n
            }
            #pragma unroll
            for (int mt = 0; mt < 4; mt++) {
                #pragma unroll
                for (int bt = 0; bt < 2; bt++) {
                    MMA16816(acc[mt][bt * 2 + 0], ra[mt], rb[bt][0], rb[bt][2]);
                    MMA16816(acc[mt][bt * 2 + 1], ra[mt], rb[bt][1], rb[bt][3]);
                }
            }
        }
    }

    // epilogue
    const bool relu = (flags & 1) != 0;
    const bool resid = (flags & 2) != 0;
    const bool half_out = (flags & 4) != 0;
    #pragma unroll
    for (int mt = 0; mt < 4; mt++) {
        #pragma unroll
        for (int nt = 0; nt < 4; nt++) {
            int gr = row0 + warpM * 64 + mt * 16 + (lane >> 2);
            int gc = col0 + warpN * 32 + (nt >> 1) * 16 + (nt & 1) * 8 +
                     (lane & 3) * 2;
            float2 b2 = *(const float2*)(Bias + gc);
            #pragma unroll
            for (int h = 0; h < 2; h++) {
                int row = gr + h * 8;
                if (row >= M) continue;
                float v0 = acc[mt][nt][h * 2 + 0] + b2.x;
                float v1 = acc[mt][nt][h * 2 + 1] + b2.y;
                if (relu) { v0 = fmaxf(v0, 0.f); v1 = fmaxf(v1, 0.f); }
                if (resid) {
                    float2 rv = *(const float2*)(Res + (size_t)row * 512 + gc);
                    v0 += rv.x; v1 += rv.y;
                }
                if (half_out) {
                    __half2 hv = __floats2half2_rn(v0, v1);
                    *(__half2*)(Ch + (size_t)row * 512 + gc) = hv;
                } else {
                    *(float2*)(C + (size_t)row * 512 + gc) = make_float2(v0, v1);
                }
            }
        }
    }
}

// ---------------- sparse attention (fp16 operands): 1 block/node, 1 warp/head ------
__global__ void k_attn() {
    int n = blockIdx.x;
    int warp = threadIdx.x >> 5;
    int lane = threadIdx.x & 31;
    int beg = g_rowptr[n], end = g_rowptr[n + 1];
    const float scale = 0.08838834764831845f;   // 1/sqrt(128)
    size_t base = (size_t)n * DIM + warp * DH + lane * 4;
    uint2 qu = *(const uint2*)&g_q16[base];
    float2 q01 = __half22float2(*(__half2*)&qu.x);
    float2 q23 = __half22float2(*(__half2*)&qu.y);
    float m = -INFINITY, s = 0.0f;
    float a0 = 0.f, a1 = 0.f, a2 = 0.f, a3 = 0.f;
    for (int e = beg; e < end; e++) {
        int d = g_csrdst[e];
        size_t kb = (size_t)d * DIM + warp * DH + lane * 4;
        uint2 ku = *(const uint2*)&g_k16[kb];
        float2 k01 = __half22float2(*(__half2*)&ku.x);
        float2 k23 = __half22float2(*(__half2*)&ku.y);
        float p = q01.x * k01.x + q01.y * k01.y + q23.x * k23.x + q23.y * k23.y;
        p += __shfl_xor_sync(0xffffffffu, p, 16);
        p += __shfl_xor_sync(0xffffffffu, p, 8);
        p += __shfl_xor_sync(0xffffffffu, p, 4);
        p += __shfl_xor_sync(0xffffffffu, p, 2);
        p += __shfl_xor_sync(0xffffffffu, p, 1);
        float score = p * scale;
        uint2 vu = *(const uint2*)&g_v16[kb];
        float2 v01 = __half22float2(*(__half2*)&vu.x);
        float2 v23 = __half22float2(*(__half2*)&vu.y);
        float mn = fmaxf(m, score);
        float corr = expf(m - mn);
        float w = expf(score - mn);
        s = s * corr + w;
        a0 = fmaf(w, v01.x, a0 * corr);
        a1 = fmaf(w, v01.y, a1 * corr);
        a2 = fmaf(w, v23.x, a2 * corr);
        a3 = fmaf(w, v23.y, a3 * corr);
        m = mn;
    }
    float inv = (end > beg) ? (1.0f / s) : 0.0f;
    __half2 h01 = __floats2half2_rn(a0 * inv, a1 * inv);
    __half2 h23 = __floats2half2_rn(a2 * inv, a3 * inv);
    *(uint2*)(g_attn16 + base) = make_uint2(*(uint32_t*)&h01, *(uint32_t*)&h23);
}

// ---------------- host ----------------
extern "C" void kernel_launch(void* const* d_in, const int* in_sizes, int n_in,
                              void* d_out, int out_size) {
    const float* x_in  = (const float*)d_in[0];
    const int*   edge  = (const int*)d_in[1];
    const float* noise = (const float*)d_in[2];
    const float* f_w1 = (const float*)d_in[3];
    const float* f_b1 = (const float*)d_in[4];
    const float* f_w2 = (const float*)d_in[5];
    const float* f_b2 = (const float*)d_in[6];
    const float* s1_w = (const float*)d_in[7];
    const float* s1_b = (const float*)d_in[8];
    const float* b1_w = (const float*)d_in[9];
    const float* b1_b = (const float*)d_in[10];
    const float* wq = (const float*)d_in[11];
    const float* bq = (const float*)d_in[12];
    const float* wk = (const float*)d_in[13];
    const float* bk = (const float*)d_in[14];
    const float* wv = (const float*)d_in[15];
    const float* bv = (const float*)d_in[16];
    const float* wo = (const float*)d_in[17];
    const float* bo = (const float*)d_in[18];
    const float* s2_w = (const float*)d_in[19];
    const float* s2_b = (const float*)d_in[20];
    const float* b2_w = (const float*)d_in[21];
    const float* b2_b = (const float*)d_in[22];
    const float* m_w1 = (const float*)d_in[23];
    const float* m_b1 = (const float*)d_in[24];
    const float* m_w2 = (const float*)d_in[25];
    const float* m_b2 = (const float*)d_in[26];

    float* x = (float*)d_out;

    static bool attr_set = false;
    if (!attr_set) {
        cudaFuncSetAttribute(k_gemm_hmma, cudaFuncAttributeMaxDynamicSharedMemorySize,
                             GEMM_SMEM);
        attr_set = true;
    }

    __half *q16, *k16, *v16, *yp16, *ap16, *hp16;
    cudaGetSymbolAddress((void**)&q16, g_q16);
    cudaGetSymbolAddress((void**)&k16, g_k16);
    cudaGetSymbolAddress((void**)&v16, g_v16);
    cudaGetSymbolAddress((void**)&yp16, g_y16);
    cudaGetSymbolAddress((void**)&ap16, g_attn16);
    cudaGetSymbolAddress((void**)&hp16, g_h16);

    cudaMemcpyAsync(x, x_in, (size_t)N_NODES * DIM * sizeof(float),
                    cudaMemcpyDeviceToDevice);

    // CSR build
    k_zero_deg<<<(N_NODES + 255) / 256, 256>>>();
    k_count_deg<<<(N_EDGES + 255) / 256, 256>>>(edge);
    k_scan_deg<<<1, 1024>>>();
    k_scatter_edges<<<(N_EDGES + 255) / 256, 256>>>(edge);

    // weight prep + conditioning
    k_prep_w<<<dim3(16, 16, 24), dim3(32, 8)>>>(wq, wk, wv, wo, m_w1, m_w2);
    k_cond<<<(N_NODES + 127) / 128, 128>>>(noise, f_w1, f_b1, f_w2, f_b2);

    dim3 ggrid(4, (N_NODES + 127) / 128);
    for (int b = 0; b < NB; b++) {
        const size_t bOff = (size_t)b * DIM;
        const size_t cOff = (size_t)b * CDIM * DIM;
        const int slot = b * 6;

        k_cln<<<N_NODES, 128>>>(x, s1_w + cOff, s1_b + bOff, b1_w + cOff, b1_b + bOff);
        k_gemm_hmma<<<ggrid, 256, GEMM_SMEM>>>(yp16, slot + 0, bq + bOff, nullptr, nullptr, q16, N_NODES, 4);
        k_gemm_hmma<<<ggrid, 256, GEMM_SMEM>>>(yp16, slot + 1, bk + bOff, nullptr, nullptr, k16, N_NODES, 4);
        k_gemm_hmma<<<ggrid, 256, GEMM_SMEM>>>(yp16, slot + 2, bv + bOff, nullptr, nullptr, v16, N_NODES, 4);
        k_attn<<<N_NODES, 128>>>();
        k_gemm_hmma<<<ggrid, 256, GEMM_SMEM>>>(ap16, slot + 3, bo + bOff, x, x, nullptr, N_NODES, 2);
        k_cln<<<N_NODES, 128>>>(x, s2_w + cOff, s2_b + bOff, b2_w + cOff, b2_b + bOff);
        k_gemm_hmma<<<ggrid, 256, GEMM_SMEM>>>(yp16, slot + 4, m_b1 + bOff, nullptr, nullptr, hp16, N_NODES, 5);
        k_gemm_hmma<<<ggrid, 256, GEMM_SMEM>>>(hp16, slot + 5, m_b2 + bOff, x, x, nullptr, N_NODES, 2);
    }
}

// round 6
// speedup vs baseline: 4.8132x; 1.6167x over previous
#include <cuda_runtime.h>
#include <cuda_fp16.h>
#include <math.h>
#include <stdint.h>

#define N_NODES 40962
#define DIM 512
#define N_EDGES 655392
#define NB 4
#define NHEADS 4
#define DH 128
#define CDIM 16
#define NFREQ 32

// ---------------- scratch (device globals; no allocation allowed) ----------------
__device__ __half g_qkv16[(size_t)N_NODES * 1536];   // packed q|k|v per node
__device__ __half g_y16[(size_t)N_NODES * DIM];
__device__ __half g_attn16[(size_t)N_NODES * DIM];
__device__ __half g_h16[(size_t)N_NODES * DIM];
__device__ __half g_cond16[(size_t)N_NODES * 32];    // cond(16) | 1.0 | zeros
__device__ __half g_film_t[32ull * 8192];            // FiLM tables, K-major
__device__ __half g_film[(size_t)N_NODES * 8192];    // per-node scale/bias, all blocks
__device__ float g_bqkv[4 * 1536];
__device__ int g_deg[N_NODES];
__device__ int g_rowptr[N_NODES + 1];
__device__ int g_cursor[N_NODES];
__device__ int g_csrdst[N_EDGES];
// weights transposed to [N,K] fp16.  24 slots = 4 blocks x {q,k,v,o,m1,m2}
__device__ __half g_wt[24ull * 512 * 512];

// ---------------- helpers ----------------
__device__ __forceinline__ uint32_t smem_u32(const void* p) {
    uint32_t a;
    asm("{ .reg .u64 t; cvta.to.shared.u64 t, %1; cvt.u32.u64 %0, t; }"
        : "=r"(a) : "l"(p));
    return a;
}

#define LDSM4(r, addr) \
    asm volatile("ldmatrix.sync.aligned.m8n8.x4.shared.b16 {%0,%1,%2,%3}, [%4];" \
        : "=r"((r)[0]), "=r"((r)[1]), "=r"((r)[2]), "=r"((r)[3]) : "r"(addr))

#define LDSM4T(r, addr) \
    asm volatile("ldmatrix.sync.aligned.m8n8.x4.trans.shared.b16 {%0,%1,%2,%3}, [%4];" \
        : "=r"((r)[0]), "=r"((r)[1]), "=r"((r)[2]), "=r"((r)[3]) : "r"(addr))

#define MMA16816(d, a, b0, b1) \
    asm volatile("mma.sync.aligned.m16n8k16.row.col.f32.f16.f16.f32 " \
        "{%0,%1,%2,%3}, {%4,%5,%6,%7}, {%8,%9}, {%0,%1,%2,%3};" \
        : "+f"((d)[0]), "+f"((d)[1]), "+f"((d)[2]), "+f"((d)[3]) \
        : "r"((a)[0]), "r"((a)[1]), "r"((a)[2]), "r"((a)[3]), "r"(b0), "r"(b1))

#define CP_ASYNC16(dst, src, sz) \
    asm volatile("cp.async.cg.shared.global [%0], [%1], 16, %2;" \
        :: "r"(dst), "l"(src), "r"(sz) : "memory")
#define CP_COMMIT() asm volatile("cp.async.commit_group;" ::: "memory")
#define CP_WAIT(N)  asm volatile("cp.async.wait_group %0;" :: "n"(N) : "memory")

// ---------------- Fourier noise embedding + cond MLP -> fp16 cond_ext ----------------
__global__ void k_cond(const float* __restrict__ noise,
                       const float* __restrict__ fw1, const float* __restrict__ fb1,
                       const float* __restrict__ fw2, const float* __restrict__ fb2) {
    __shared__ float s_w1[2 * NFREQ * CDIM];
    __shared__ float s_w2[CDIM * CDIM];
    __shared__ float s_b1[CDIM];
    __shared__ float s_b2[CDIM];
    for (int i = threadIdx.x; i < 2 * NFREQ * CDIM; i += blockDim.x) s_w1[i] = fw1[i];
    for (int i = threadIdx.x; i < CDIM * CDIM; i += blockDim.x) s_w2[i] = fw2[i];
    if (threadIdx.x < CDIM) {
        s_b1[threadIdx.x] = fb1[threadIdx.x];
        s_b2[threadIdx.x] = fb2[threadIdx.x];
    }
    __syncthreads();
    int n = blockIdx.x * blockDim.x + threadIdx.x;
    if (n >= N_NODES) return;
    float t = noise[n];
    const float w0 = 2.0f * 3.14159265358979323846f / 16.0f;
    float emb[2 * NFREQ];
    #pragma unroll
    for (int f = 0; f < NFREQ; f++) {
        float ph = t * (w0 * (float)(f + 1));
        emb[f] = sinf(ph);
        emb[NFREQ + f] = cosf(ph);
    }
    float h[CDIM];
    #pragma unroll
    for (int c = 0; c < CDIM; c++) {
        float acc = s_b1[c];
        #pragma unroll
        for (int f = 0; f < 2 * NFREQ; f++) acc = fmaf(emb[f], s_w1[f * CDIM + c], acc);
        h[c] = acc / (1.0f + expf(-acc));
    }
    __half* out = g_cond16 + (size_t)n * 32;
    #pragma unroll
    for (int c2 = 0; c2 < CDIM; c2++) {
        float acc = s_b2[c2];
        #pragma unroll
        for (int c = 0; c < CDIM; c++) acc = fmaf(h[c], s_w2[c * CDIM + c2], acc);
        out[c2] = __float2half_rn(acc);
    }
    out[16] = __float2half_rn(1.0f);
    #pragma unroll
    for (int c2 = 17; c2 < 32; c2++) out[c2] = __float2half_rn(0.0f);
}

// ---------------- weight prep: transpose fp32 W[K,N] -> fp16 WT[N,K] ----------------
__global__ void k_prep_w(const float* __restrict__ wq, const float* __restrict__ wk,
                         const float* __restrict__ wv, const float* __restrict__ wo,
                         const float* __restrict__ w1, const float* __restrict__ w2) {
    int slot = blockIdx.z;
    int b = slot / 6, t = slot % 6;
    const float* W =
        (t == 0 ? wq : t == 1 ? wk : t == 2 ? wv : t == 3 ? wo : t == 4 ? w1 : w2) +
        (size_t)b * 512 * 512;
    __shared__ float tile[32][33];
    int x0 = blockIdx.x * 32, y0 = blockIdx.y * 32;
    int tx = threadIdx.x, ty = threadIdx.y;
    #pragma unroll
    for (int r = 0; r < 32; r += 8)
        tile[ty + r][tx] = W[(size_t)(y0 + ty + r) * 512 + x0 + tx];
    __syncthreads();
    size_t base = (size_t)slot * 512 * 512;
    #pragma unroll
    for (int r = 0; r < 32; r += 8) {
        float v = tile[tx][ty + r];
        g_wt[base + (size_t)(x0 + ty + r) * 512 + y0 + tx] = __float2half_rn(v);
    }
}

// ---------------- FiLM table build + packed qkv bias ----------------
// film_t column layout: col = b*2048 + ln*1024 + which*512 + d
//   which=0 -> scale table (s*_w rows 0-15, s*_b row 16), which=1 -> bias table
__global__ void k_film_tab(const float* __restrict__ s1w, const float* __restrict__ s1b,
                           const float* __restrict__ b1w, const float* __restrict__ b1b,
                           const float* __restrict__ s2w, const float* __restrict__ s2b,
                           const float* __restrict__ b2w, const float* __restrict__ b2b,
                           const float* __restrict__ bq, const float* __restrict__ bk,
                           const float* __restrict__ bv) {
    int idx = blockIdx.x * blockDim.x + threadIdx.x;
    if (idx < 32 * 8192) {
        int c = idx >> 13, col = idx & 8191;
        int b = col >> 11, ln = (col >> 10) & 1, which = (col >> 9) & 1, d = col & 511;
        float v = 0.0f;
        if (c < 16) {
            const float* W = which == 0 ? (ln ? s2w : s1w) : (ln ? b2w : b1w);
            v = W[(size_t)b * CDIM * DIM + c * DIM + d];
        } else if (c == 16) {
            const float* Bv = which == 0 ? (ln ? s2b : s1b) : (ln ? b2b : b1b);
            v = Bv[b * DIM + d];
        }
        g_film_t[(size_t)c * 8192 + col] = __float2half_rn(v);
    } else {
        int bi = idx - 32 * 8192;
        if (bi < 4 * 1536) {
            int b = bi / 1536, j = bi % 1536;
            const float* src = j < 512 ? bq : (j < 1024 ? bk : bv);
            g_bqkv[b * 1536 + j] = src[b * 512 + (j & 511)];
        }
    }
}

// ---------------- FiLM GEMM: film(N x 8192) = cond_ext(N x 32) @ film_t(32 x 8192) --
#define FA_PITCH 40
#define FB_PITCH 136
__global__ __launch_bounds__(256) void k_film() {
    __shared__ __half sA[128 * FA_PITCH];
    __shared__ __half sB[32 * FB_PITCH];
    const int tid = threadIdx.x, lane = tid & 31, wid = tid >> 5;
    const int warpM = wid >> 2, warpN = wid & 3;
    const int col0 = blockIdx.x * 128, row0 = blockIdx.y * 128;

    #pragma unroll
    for (int i = 0; i < 2; i++) {
        int v = i * 256 + tid;
        int r = v >> 2, q = v & 3;
        uint4 val = make_uint4(0, 0, 0, 0);
        if (row0 + r < N_NODES)
            val = *(const uint4*)(g_cond16 + (size_t)(row0 + r) * 32 + q * 8);
        *(uint4*)(sA + r * FA_PITCH + q * 8) = val;
    }
    #pragma unroll
    for (int i = 0; i < 2; i++) {
        int v = i * 256 + tid;
        int r = v >> 4, q = v & 15;
        uint4 val = *(const uint4*)(g_film_t + (size_t)r * 8192 + col0 + q * 8);
        *(uint4*)(sB + r * FB_PITCH + q * 8) = val;
    }
    __syncthreads();

    float acc[4][4][4];
    #pragma unroll
    for (int i = 0; i < 4; i++)
        #pragma unroll
        for (int j = 0; j < 4; j++)
            #pragma unroll
            for (int r = 0; r < 4; r++) acc[i][j][r] = 0.0f;

    const uint32_t saB = smem_u32(sA), sbB = smem_u32(sB);
    const int aRow = lane & 15, aHi = lane >> 4;
    #pragma unroll
    for (int ks = 0; ks < 2; ks++) {
        uint32_t ra[4][4], rb[2][4];
        #pragma unroll
        for (int mt = 0; mt < 4; mt++) {
            uint32_t addr = saB +
                (uint32_t)(((warpM * 64 + mt * 16 + aRow) * FA_PITCH + ks * 16 + aHi * 8) * 2);
            LDSM4(ra[mt], addr);
        }
        #pragma unroll
        for (int bt = 0; bt < 2; bt++) {
            uint32_t addr = sbB +
                (uint32_t)(((ks * 16 + aRow) * FB_PITCH + warpN * 32 + bt * 16 + aHi * 8) * 2);
            LDSM4T(rb[bt], addr);   // B stored [k][n] -> trans gives k-pairs per n
        }
        #pragma unroll
        for (int mt = 0; mt < 4; mt++) {
            #pragma unroll
            for (int bt = 0; bt < 2; bt++) {
                MMA16816(acc[mt][bt * 2 + 0], ra[mt], rb[bt][0], rb[bt][1]);
                MMA16816(acc[mt][bt * 2 + 1], ra[mt], rb[bt][2], rb[bt][3]);
            }
        }
    }

    #pragma unroll
    for (int mt = 0; mt < 4; mt++) {
        #pragma unroll
        for (int nt = 0; nt < 4; nt++) {
            int gr = row0 + warpM * 64 + mt * 16 + (lane >> 2);
            int gc = col0 + warpN * 32 + (nt >> 1) * 16 + (nt & 1) * 8 + (lane & 3) * 2;
            #pragma unroll
            for (int h = 0; h < 2; h++) {
                int row = gr + h * 8;
                if (row >= N_NODES) continue;
                __half2 hv = __floats2half2_rn(acc[mt][nt][h * 2 + 0],
                                               acc[mt][nt][h * 2 + 1]);
                *(__half2*)(g_film + (size_t)row * 8192 + gc) = hv;
            }
        }
    }
}

// ---------------- CSR build ----------------
__global__ void k_zero_deg() {
    int i = blockIdx.x * blockDim.x + threadIdx.x;
    if (i < N_NODES) g_deg[i] = 0;
}

__global__ void k_count_deg(const int* __restrict__ edge) {
    int e = blockIdx.x * blockDim.x + threadIdx.x;
    if (e < N_EDGES) atomicAdd(&g_deg[edge[e]], 1);
}

__global__ void k_scan_deg() {
    __shared__ int partial[1024];
    const int tid = threadIdx.x;
    const int CH = (N_NODES + 1023) / 1024;
    const int base = tid * CH;
    int sum = 0;
    for (int i = 0; i < CH; i++) {
        int idx = base + i;
        if (idx < N_NODES) sum += g_deg[idx];
    }
    partial[tid] = sum;
    __syncthreads();
    for (int off = 1; off < 1024; off <<= 1) {
        int t = (tid >= off) ? partial[tid - off] : 0;
        __syncthreads();
        partial[tid] += t;
        __syncthreads();
    }
    int offset = (tid > 0) ? partial[tid - 1] : 0;
    for (int i = 0; i < CH; i++) {
        int idx = base + i;
        if (idx < N_NODES) {
            g_rowptr[idx] = offset;
            g_cursor[idx] = offset;
            offset += g_deg[idx];
        }
    }
    if (tid == 1023) g_rowptr[N_NODES] = partial[1023];
}

__global__ void k_scatter_edges(const int* __restrict__ edge) {
    int e = blockIdx.x * blockDim.x + threadIdx.x;
    if (e < N_EDGES) {
        int s = edge[e];
        int d = edge[N_EDGES + e];
        int p = atomicAdd(&g_cursor[s], 1);
        g_csrdst[p] = d;
    }
}

// ---------------- conditional LayerNorm (FiLM, precomputed) -> fp16 ----------------
__global__ void k_cln(const float* __restrict__ x, const __half* __restrict__ film) {
    int n = blockIdx.x;
    int tid = threadIdx.x;
    __shared__ float s_red[8];
    float4 xv = *(const float4*)(x + (size_t)n * DIM + tid * 4);
    float s = xv.x + xv.y + xv.z + xv.w;
    float s2 = fmaf(xv.x, xv.x, fmaf(xv.y, xv.y, fmaf(xv.z, xv.z, xv.w * xv.w)));
    #pragma unroll
    for (int o = 16; o; o >>= 1) {
        s += __shfl_xor_sync(0xffffffffu, s, o);
        s2 += __shfl_xor_sync(0xffffffffu, s2, o);
    }
    int w = tid >> 5, l = tid & 31;
    if (l == 0) { s_red[w] = s; s_red[4 + w] = s2; }
    __syncthreads();
    s = s_red[0] + s_red[1] + s_red[2] + s_red[3];
    s2 = s_red[4] + s_red[5] + s_red[6] + s_red[7];
    float mu = s * (1.0f / DIM);
    float var = s2 * (1.0f / DIM) - mu * mu;
    float inv = rsqrtf(var + 1e-5f);
    int d0 = tid * 4;
    const __half* frow = film + (size_t)n * 8192;
    uint2 su = *(const uint2*)(frow + d0);
    uint2 bu = *(const uint2*)(frow + 512 + d0);
    float2 s01 = __half22float2(*(__half2*)&su.x);
    float2 s23 = __half22float2(*(__half2*)&su.y);
    float2 b01 = __half22float2(*(__half2*)&bu.x);
    float2 b23 = __half22float2(*(__half2*)&bu.y);
    float o0 = (xv.x - mu) * inv * (1.0f + s01.x) + b01.x;
    float o1 = (xv.y - mu) * inv * (1.0f + s01.y) + b01.y;
    float o2 = (xv.z - mu) * inv * (1.0f + s23.x) + b23.x;
    float o3 = (xv.w - mu) * inv * (1.0f + s23.y) + b23.y;
    __half2 h01 = __floats2half2_rn(o0, o1);
    __half2 h23 = __floats2half2_rn(o2, o3);
    *(uint2*)(g_y16 + (size_t)n * DIM + d0) =
        make_uint2(*(uint32_t*)&h01, *(uint32_t*)&h23);
}

// ---------------- HMMA GEMM: 128x128x64 tiles, 3-stage cp.async pipeline ----------
// flags: bit0 relu, bit1 residual(+Res fp32), bit2 fp16 out (to Ch, stride ldc)
#define SPITCH 72
#define AB_OFF (128 * SPITCH * 2)
#define STAGE_BYTES (256 * SPITCH * 2)
#define NSTAGE 3
#define GEMM_SMEM (NSTAGE * STAGE_BYTES)

__device__ __forceinline__ void g_load_stage(
    const __half* __restrict__ A, const __half* __restrict__ WT,
    uint32_t sbase, int row0, int k0, int M, int tid) {
    #pragma unroll
    for (int i = 0; i < 4; i++) {
        int v = i * 256 + tid;
        int r = v >> 3, q = v & 7;
        uint32_t dst = sbase + (uint32_t)(r * (SPITCH * 2) + q * 16);
        const __half* src = A + (size_t)(row0 + r) * 512 + k0 + q * 8;
        int sz = (row0 + r < M) ? 16 : 0;
        CP_ASYNC16(dst, src, sz);
    }
    #pragma unroll
    for (int i = 0; i < 4; i++) {
        int v = i * 256 + tid;
        int r = v >> 3, q = v & 7;
        uint32_t dst = sbase + AB_OFF + (uint32_t)(r * (SPITCH * 2) + q * 16);
        const __half* src = WT + (size_t)r * 512 + k0 + q * 8;
        CP_ASYNC16(dst, src, 16);
    }
    CP_COMMIT();
}

__global__ __launch_bounds__(256) void k_gemm_hmma(
    const __half* __restrict__ A, int slot,
    const float* __restrict__ Bias, const float* __restrict__ Res,
    float* __restrict__ C, __half* __restrict__ Ch, int ldc, int M, int flags) {
    extern __shared__ __align__(128) char smem[];
    const int tid = threadIdx.x;
    const int lane = tid & 31, wid = tid >> 5;
    const int warpM = wid >> 2, warpN = wid & 3;
    const int col0 = blockIdx.x * 128, row0 = blockIdx.y * 128;
    const __half* WT = g_wt + (size_t)slot * 512 * 512 + (size_t)col0 * 512;
    const uint32_t sb = smem_u32(smem);

    float acc[4][4][4];
    #pragma unroll
    for (int i = 0; i < 4; i++)
        #pragma unroll
        for (int j = 0; j < 4; j++)
            #pragma unroll
            for (int r = 0; r < 4; r++) acc[i][j][r] = 0.0f;

    g_load_stage(A, WT, sb, row0, 0, M, tid);
    g_load_stage(A, WT, sb + STAGE_BYTES, row0, 64, M, tid);

    const int aRow = lane & 15, aHi = lane >> 4;
    #pragma unroll 1
    for (int it = 0; it < 8; it++) {
        if (it < 7) { CP_WAIT(1); } else { CP_WAIT(0); }
        __syncthreads();
        if (it < 6)
            g_load_stage(A, WT, sb + (uint32_t)((it + 2) % NSTAGE) * STAGE_BYTES,
                         row0, (it + 2) * 64, M, tid);

        uint32_t aB = sb + (uint32_t)(it % NSTAGE) * STAGE_BYTES;
        uint32_t bB = aB + AB_OFF;
        #pragma unroll
        for (int ks = 0; ks < 4; ks++) {
            uint32_t ra[4][4], rb[2][4];
            #pragma unroll
            for (int mt = 0; mt < 4; mt++) {
                uint32_t addr = aB +
                    (uint32_t)((warpM * 64 + mt * 16 + aRow) * (SPITCH * 2) +
                               ks * 32 + aHi * 16);
                LDSM4(ra[mt], addr);
            }
            #pragma unroll
            for (int bt = 0; bt < 2; bt++) {
                uint32_t addr = bB +
                    (uint32_t)((warpN * 32 + bt * 16 + aRow) * (SPITCH * 2) +
                               ks * 32 + aHi * 16);
                LDSM4(rb[bt], addr);
            }
            #pragma unroll
            for (int mt = 0; mt < 4; mt++) {
                #pragma unroll
                for (int bt = 0; bt < 2; bt++) {
                    MMA16816(acc[mt][bt * 2 + 0], ra[mt], rb[bt][0], rb[bt][2]);
                    MMA16816(acc[mt][bt * 2 + 1], ra[mt], rb[bt][1], rb[bt][3]);
                }
            }
        }
    }

    const bool relu = (flags & 1) != 0;
    const bool resid = (flags & 2) != 0;
    const bool half_out = (flags & 4) != 0;
    #pragma unroll
    for (int mt = 0; mt < 4; mt++) {
        #pragma unroll
        for (int nt = 0; nt < 4; nt++) {
            int gr = row0 + warpM * 64 + mt * 16 + (lane >> 2);
            int gc = col0 + warpN * 32 + (nt >> 1) * 16 + (nt & 1) * 8 + (lane & 3) * 2;
            float2 b2 = *(const float2*)(Bias + gc);
            #pragma unroll
            for (int h = 0; h < 2; h++) {
                int row = gr + h * 8;
                if (row >= M) continue;
                float v0 = acc[mt][nt][h * 2 + 0] + b2.x;
                float v1 = acc[mt][nt][h * 2 + 1] + b2.y;
                if (relu) { v0 = fmaxf(v0, 0.f); v1 = fmaxf(v1, 0.f); }
                if (resid) {
                    float2 rv = *(const float2*)(Res + (size_t)row * 512 + gc);
                    v0 += rv.x; v1 += rv.y;
                }
                if (half_out) {
                    __half2 hv = __floats2half2_rn(v0, v1);
                    *(__half2*)(Ch + (size_t)row * ldc + gc) = hv;
                } else {
                    *(float2*)(C + (size_t)row * 512 + gc) = make_float2(v0, v1);
                }
            }
        }
    }
}

// ---------------- sparse attention (packed fp16 qkv): 1 block/node, 1 warp/head ----
__global__ void k_attn() {
    int n = blockIdx.x;
    int warp = threadIdx.x >> 5;
    int lane = threadIdx.x & 31;
    int beg = g_rowptr[n], end = g_rowptr[n + 1];
    const float scale = 0.08838834764831845f;   // 1/sqrt(128)
    int hoff = warp * DH + lane * 4;
    uint2 qu = *(const uint2*)&g_qkv16[(size_t)n * 1536 + hoff];
    float2 q01 = __half22float2(*(__half2*)&qu.x);
    float2 q23 = __half22float2(*(__half2*)&qu.y);
    float m = -INFINITY, s = 0.0f;
    float a0 = 0.f, a1 = 0.f, a2 = 0.f, a3 = 0.f;
    int koff = hoff + 512;
    int e = beg;
    for (; e + 2 <= end; e += 2) {
        int d0 = g_csrdst[e], d1 = g_csrdst[e + 1];
        const __half* r0 = g_qkv16 + (size_t)d0 * 1536 + koff;
        const __half* r1 = g_qkv16 + (size_t)d1 * 1536 + koff;
        uint2 k0u = *(const uint2*)r0;
        uint2 k1u = *(const uint2*)r1;
        uint2 v0u = *(const uint2*)(r0 + 512);
        uint2 v1u = *(const uint2*)(r1 + 512);
        float2 k01 = __half22float2(*(__half2*)&k0u.x);
        float2 k23 = __half22float2(*(__half2*)&k0u.y);
        float p0 = q01.x * k01.x + q01.y * k01.y + q23.x * k23.x + q23.y * k23.y;
        float2 l01 = __half22float2(*(__half2*)&k1u.x);
        float2 l23 = __half22float2(*(__half2*)&k1u.y);
        float p1 = q01.x * l01.x + q01.y * l01.y + q23.x * l23.x + q23.y * l23.y;
        #pragma unroll
        for (int o = 16; o; o >>= 1) {
            p0 += __shfl_xor_sync(0xffffffffu, p0, o);
            p1 += __shfl_xor_sync(0xffffffffu, p1, o);
        }
        p0 *= scale; p1 *= scale;
        float2 v01 = __half22float2(*(__half2*)&v0u.x);
        float2 v23 = __half22float2(*(__half2*)&v0u.y);
        float mn = fmaxf(m, p0);
        float corr = expf(m - mn);
        float w = expf(p0 - mn);
        s = s * corr + w;
        a0 = fmaf(w, v01.x, a0 * corr);
        a1 = fmaf(w, v01.y, a1 * corr);
        a2 = fmaf(w, v23.x, a2 * corr);
        a3 = fmaf(w, v23.y, a3 * corr);
        m = mn;
        float2 u01 = __half22float2(*(__half2*)&v1u.x);
        float2 u23 = __half22float2(*(__half2*)&v1u.y);
        mn = fmaxf(m, p1);
        corr = expf(m - mn);
        w = expf(p1 - mn);
        s = s * corr + w;
        a0 = fmaf(w, u01.x, a0 * corr);
        a1 = fmaf(w, u01.y, a1 * corr);
        a2 = fmaf(w, u23.x, a2 * corr);
        a3 = fmaf(w, u23.y, a3 * corr);
        m = mn;
    }
    if (e < end) {
        int d = g_csrdst[e];
        const __half* r0 = g_qkv16 + (size_t)d * 1536 + koff;
        uint2 ku = *(const uint2*)r0;
        uint2 vu = *(const uint2*)(r0 + 512);
        float2 k01 = __half22float2(*(__half2*)&ku.x);
        float2 k23 = __half22float2(*(__half2*)&ku.y);
        float p = q01.x * k01.x + q01.y * k01.y + q23.x * k23.x + q23.y * k23.y;
        #pragma unroll
        for (int o = 16; o; o >>= 1) p += __shfl_xor_sync(0xffffffffu, p, o);
        p *= scale;
        float2 v01 = __half22float2(*(__half2*)&vu.x);
        float2 v23 = __half22float2(*(__half2*)&vu.y);
        float mn = fmaxf(m, p);
        float corr = expf(m - mn);
        float w = expf(p - mn);
        s = s * corr + w;
        a0 = fmaf(w, v01.x, a0 * corr);
        a1 = fmaf(w, v01.y, a1 * corr);
        a2 = fmaf(w, v23.x, a2 * corr);
        a3 = fmaf(w, v23.y, a3 * corr);
        m = mn;
    }
    float inv = (end > beg) ? (1.0f / s) : 0.0f;
    __half2 h01 = __floats2half2_rn(a0 * inv, a1 * inv);
    __half2 h23 = __floats2half2_rn(a2 * inv, a3 * inv);
    *(uint2*)(g_attn16 + (size_t)n * DIM + hoff) =
        make_uint2(*(uint32_t*)&h01, *(uint32_t*)&h23);
}

// ---------------- host ----------------
extern "C" void kernel_launch(void* const* d_in, const int* in_sizes, int n_in,
                              void* d_out, int out_size) {
    const float* x_in  = (const float*)d_in[0];
    const int*   edge  = (const int*)d_in[1];
    const float* noise = (const float*)d_in[2];
    const float* f_w1 = (const float*)d_in[3];
    const float* f_b1 = (const float*)d_in[4];
    const float* f_w2 = (const float*)d_in[5];
    const float* f_b2 = (const float*)d_in[6];
    const float* s1_w = (const float*)d_in[7];
    const float* s1_b = (const float*)d_in[8];
    const float* b1_w = (const float*)d_in[9];
    const float* b1_b = (const float*)d_in[10];
    const float* wq = (const float*)d_in[11];
    const float* bq = (const float*)d_in[12];
    const float* wk = (const float*)d_in[13];
    const float* bk = (const float*)d_in[14];
    const float* wv = (const float*)d_in[15];
    const float* bv = (const float*)d_in[16];
    const float* wo = (const float*)d_in[17];
    const float* bo = (const float*)d_in[18];
    const float* s2_w = (const float*)d_in[19];
    const float* s2_b = (const float*)d_in[20];
    const float* b2_w = (const float*)d_in[21];
    const float* b2_b = (const float*)d_in[22];
    const float* m_w1 = (const float*)d_in[23];
    const float* m_b1 = (const float*)d_in[24];
    const float* m_w2 = (const float*)d_in[25];
    const float* m_b2 = (const float*)d_in[26];

    float* x = (float*)d_out;

    static bool attr_set = false;
    if (!attr_set) {
        cudaFuncSetAttribute(k_gemm_hmma, cudaFuncAttributeMaxDynamicSharedMemorySize,
                             GEMM_SMEM);
        attr_set = true;
    }

    __half *qkv16, *yp16, *ap16, *hp16, *film;
    float *bqkv;
    cudaGetSymbolAddress((void**)&qkv16, g_qkv16);
    cudaGetSymbolAddress((void**)&yp16, g_y16);
    cudaGetSymbolAddress((void**)&ap16, g_attn16);
    cudaGetSymbolAddress((void**)&hp16, g_h16);
    cudaGetSymbolAddress((void**)&film, g_film);
    cudaGetSymbolAddress((void**)&bqkv, g_bqkv);

    cudaMemcpyAsync(x, x_in, (size_t)N_NODES * DIM * sizeof(float),
                    cudaMemcpyDeviceToDevice);

    // 0: conditioning
    k_cond<<<(N_NODES + 127) / 128, 128>>>(noise, f_w1, f_b1, f_w2, f_b2);
    // 1: weight prep
    k_prep_w<<<dim3(16, 16, 24), dim3(32, 8)>>>(wq, wk, wv, wo, m_w1, m_w2);
    // 2: FiLM tables + packed bias
    k_film_tab<<<(32 * 8192 + 4 * 1536 + 255) / 256, 256>>>(
        s1_w, s1_b, b1_w, b1_b, s2_w, s2_b, b2_w, b2_b, bq, bk, bv);
    // 3: FiLM precompute GEMM (profiled slot)
    k_film<<<dim3(64, (N_NODES + 127) / 128), 256>>>();

    dim3 gq(12, (N_NODES + 127) / 128);
    dim3 gg(4, (N_NODES + 127) / 128);
    bool csr_done = false;
    for (int b = 0; b < NB; b++) {
        const size_t bOff = (size_t)b * DIM;
        const int slot = b * 6;
        const __half* f1 = film + (size_t)b * 2048;
        const __half* f2 = f1 + 1024;

        k_cln<<<N_NODES, 128>>>(x, f1);
        k_gemm_hmma<<<gq, 256, GEMM_SMEM>>>(yp16, slot, bqkv + b * 1536, nullptr,
                                            nullptr, qkv16, 1536, N_NODES, 4);
        if (!csr_done) {
            k_zero_deg<<<(N_NODES + 255) / 256, 256>>>();
            k_count_deg<<<(N_EDGES + 255) / 256, 256>>>(edge);
            k_scan_deg<<<1, 1024>>>();
            k_scatter_edges<<<(N_EDGES + 255) / 256, 256>>>(edge);
            csr_done = true;
        }
        k_attn<<<N_NODES, 128>>>();
        k_gemm_hmma<<<gg, 256, GEMM_SMEM>>>(ap16, slot + 3, bo + bOff, x, x,
                                            nullptr, 512, N_NODES, 2);
        k_cln<<<N_NODES, 128>>>(x, f2);
        k_gemm_hmma<<<gg, 256, GEMM_SMEM>>>(yp16, slot + 4, m_b1 + bOff, nullptr,
                                            nullptr, hp16, 512, N_NODES, 5);
        k_gemm_hmma<<<gg, 256, GEMM_SMEM>>>(hp16, slot + 5, m_b2 + bOff, x, x,
                                            nullptr, 512, N_NODES, 2);
    }
}